// round 5
// baseline (speedup 1.0000x reference)
#include <cuda_runtime.h>
#include <cuda_fp16.h>
#include <cstdint>

// ---------------------------------------------------------------- constants
#define NROWS   4096
#define INFEAT  4096
#define OUTFEAT 4096
#define NCODE   256
#define KLEAF   16
#define KGLOB   4096
#define NCHUNK  32            // K chunks of 128

#define TILE_BYTES 32768      // 128 rows x 256 B (128 fp16)
// smem offsets: A0, A1, B0, B1
#define SM_A0 0
#define SM_A1 (SM_A0 + TILE_BYTES)
#define SM_B0 (SM_A1 + TILE_BYTES)
#define SM_B1 (SM_B0 + TILE_BYTES)
#define SM_TOTAL (SM_B1 + TILE_BYTES)   // 128 KB

// ---------------------------------------------------------------- scratch
__device__ __align__(16) unsigned char g_codes[NROWS * NCODE];          // 1 MB
__device__ __align__(16) __half        g_lutH[(size_t)OUTFEAT * KGLOB]; // 32 MB [o][k]

// ---------------------------------------------------------------- helpers
__device__ __forceinline__ uint32_t smem_u32(const void* p) {
    uint32_t a;
    asm("{ .reg .u64 t; cvta.to.shared.u64 t, %1; cvt.u32.u64 %0, t; }"
        : "=r"(a) : "l"(p));
    return a;
}
__device__ __forceinline__ void cp_async16(uint32_t s, const void* g) {
    asm volatile("cp.async.cg.shared.global [%0], [%1], 16;"
                 :: "r"(s), "l"(g) : "memory");
}
__device__ __forceinline__ void cp_commit() {
    asm volatile("cp.async.commit_group;" ::: "memory");
}
__device__ __forceinline__ void cp_wait0() {
    asm volatile("cp.async.wait_group 0;" ::: "memory");
}
__device__ __forceinline__ void ldsm_x4(uint32_t& r0, uint32_t& r1,
                                        uint32_t& r2, uint32_t& r3, uint32_t a) {
    asm volatile("ldmatrix.sync.aligned.m8n8.x4.shared.b16 {%0,%1,%2,%3}, [%4];"
                 : "=r"(r0), "=r"(r1), "=r"(r2), "=r"(r3) : "r"(a));
}
__device__ __forceinline__ void mma16816(float& c0, float& c1, float& c2, float& c3,
                                         uint32_t a0, uint32_t a1, uint32_t a2,
                                         uint32_t a3, uint32_t b0, uint32_t b1) {
    asm volatile(
        "mma.sync.aligned.m16n8k16.row.col.f32.f16.f16.f32 "
        "{%0,%1,%2,%3}, {%4,%5,%6,%7}, {%8,%9}, {%0,%1,%2,%3};"
        : "+f"(c0), "+f"(c1), "+f"(c2), "+f"(c3)
        : "r"(a0), "r"(a1), "r"(a2), "r"(a3), "r"(b0), "r"(b1));
}

// ---------------------------------------------------------------- encode
__global__ void __launch_bounds__(NCODE) encode_kernel(
    const float* __restrict__ input,
    const int*   __restrict__ dims,
    const float* __restrict__ thr)
{
    const int n = blockIdx.x;
    const int c = threadIdx.x;
    const int4 d4 = *reinterpret_cast<const int4*>(dims + c * 4);
    const float* row = input + (size_t)n * INFEAT;
    const float x0 = __ldg(row + d4.x);
    const float x1 = __ldg(row + d4.y);
    const float x2 = __ldg(row + d4.z);
    const float x3 = __ldg(row + d4.w);
    const float* t = thr + c * 15;
    int i = 1;
    i = 2 * i + (x0 > __ldg(t + i - 1) ? 1 : 0);
    i = 2 * i + (x1 > __ldg(t + i - 1) ? 1 : 0);
    i = 2 * i + (x2 > __ldg(t + i - 1) ? 1 : 0);
    i = 2 * i + (x3 > __ldg(t + i - 1) ? 1 : 0);
    g_codes[n * NCODE + c] = (unsigned char)(i - 16);
}

// ---------------------------------------------------------------- convert
__global__ void __launch_bounds__(256) convert_kernel(const float* __restrict__ lut)
{
    const size_t t = (size_t)blockIdx.x * 256 + threadIdx.x;
    const float4* src = reinterpret_cast<const float4*>(lut);
    const float4 a = __ldg(src + 2 * t);
    const float4 b = __ldg(src + 2 * t + 1);
    __half2 h0 = __floats2half2_rn(a.x, a.y);
    __half2 h1 = __floats2half2_rn(a.z, a.w);
    __half2 h2 = __floats2half2_rn(b.x, b.y);
    __half2 h3 = __floats2half2_rn(b.z, b.w);
    uint4 o;
    o.x = *reinterpret_cast<uint32_t*>(&h0);
    o.y = *reinterpret_cast<uint32_t*>(&h1);
    o.z = *reinterpret_cast<uint32_t*>(&h2);
    o.w = *reinterpret_cast<uint32_t*>(&h3);
    reinterpret_cast<uint4*>(g_lutH)[t] = o;
}

// ---------------------------------------------------------------- GEMM
// out[rbase..+128][obase..+128] via mma.sync m16n8k16 fp16->fp32.
// A = one-hot (built in SMEM from codes), B = g_lutH tile via cp.async.
// Tiles: 128 rows x 128 halves (256 B/row), XOR-granule swizzle:
//   addr(r, kb) = buf + r*256 + (((kb>>4) ^ (r&7))<<4) + (kb&15)
__global__ void __launch_bounds__(256, 1) gemm_kernel(float* __restrict__ out)
{
    extern __shared__ char smem[];
    const uint32_t sb = smem_u32(smem);
    const int tid  = threadIdx.x;
    const int wid  = tid >> 5;
    const int lane = tid & 31;
    const int obase = blockIdx.x * 128;
    const int rbase = blockIdx.y * 128;

    // warp tile: 32 M x 64 N. wm in [0,4), wn in [0,2)
    const int m0 = (wid & 3) * 32;
    const int n0 = (wid >> 2) * 64;

    float acc[2][8][4];
#pragma unroll
    for (int mt = 0; mt < 2; ++mt)
#pragma unroll
        for (int n = 0; n < 8; ++n)
#pragma unroll
            for (int q = 0; q < 4; ++q) acc[mt][n][q] = 0.0f;

    // ldmatrix lane addressing (precompute row + swizzle base)
    const int a_row = m0 + (lane & 15);          // + 16*mt
    const int a_hi  = lane >> 4;                 // extra k granule
    const int b_row = n0 + (lane & 7) + ((lane >> 4) << 3);  // + 16*nt
    const int b_hi  = (lane >> 3) & 1;

    // staging constants
    const int st_r  = tid >> 4;                  // B stage: row, 16 thr/row
    const int st_g  = tid & 15;                  // granule
    const uint32_t st_soff = (uint32_t)st_r * 256 + ((st_g ^ (st_r & 7)) << 4);
    const __half* st_gbase = g_lutH + (size_t)(obase + st_r) * KGLOB + st_g * 8;

    // A build: thread pair (2t,2t+1) owns row t; h selects half-row
    const int ar = tid >> 1;
    const int ah = tid & 1;
    const uint32_t az_off = (uint32_t)ar * 256 + ah * 128;   // zero region
    const unsigned char* code_g = g_codes + (size_t)(rbase + ar) * NCODE + ah * 4;

#define STAGE_B(ch, bbuf) do {                                                 \
    const __half* _g = st_gbase + (ch) * 128;                                  \
    _Pragma("unroll")                                                          \
    for (int _i = 0; _i < 8; ++_i)                                             \
        cp_async16((bbuf) + _i * 4096u + st_soff, _g + (size_t)_i * 16 * KGLOB); \
} while (0)
// note: 8 iterations cover rows st_r, st_r+16, ..., st_r+112

#define BUILD_A(ch, abuf) do {                                                 \
    _Pragma("unroll")                                                          \
    for (int _i = 0; _i < 8; ++_i)                                             \
        asm volatile("st.shared.v4.b32 [%0], {%1,%1,%1,%1};"                   \
                     :: "r"((abuf) + az_off + _i * 16), "r"(0) : "memory");    \
    const uint32_t _cw = *reinterpret_cast<const uint32_t*>(code_g + (ch) * 8); \
    _Pragma("unroll")                                                          \
    for (int _cc = 0; _cc < 4; ++_cc) {                                        \
        const int _kk = (ah * 4 + _cc) * KLEAF + (int)((_cw >> (8 * _cc)) & 0xFFu); \
        const int _kb = _kk * 2;                                               \
        const uint32_t _ad = (abuf) + (uint32_t)ar * 256                       \
            + ((((_kb >> 4) ^ (ar & 7))) << 4) + (_kb & 15);                   \
        asm volatile("st.shared.u16 [%0], %1;"                                 \
                     :: "r"(_ad), "h"((unsigned short)0x3C00u) : "memory");    \
    }                                                                          \
} while (0)

    // ---- prologue: stage chunk 0
    STAGE_B(0, sb + SM_B0);
    cp_commit();
    BUILD_A(0, sb + SM_A0);
    cp_wait0();
    __syncthreads();

    for (int ch = 0; ch < NCHUNK; ++ch) {
        const int cur = ch & 1;
        const uint32_t abuf = sb + (cur ? SM_A1 : SM_A0);
        const uint32_t bbuf = sb + (cur ? SM_B1 : SM_B0);

        if (ch < NCHUNK - 1) {
            const uint32_t abn = sb + (cur ? SM_A0 : SM_A1);
            const uint32_t bbn = sb + (cur ? SM_B0 : SM_B1);
            STAGE_B(ch + 1, bbn);
            cp_commit();
            BUILD_A(ch + 1, abn);
        }

        // ---- compute chunk: 8 k-steps of m16n8k16
#pragma unroll
        for (int s = 0; s < 8; ++s) {
            uint32_t a[2][4];
#pragma unroll
            for (int mt = 0; mt < 2; ++mt) {
                const int r = a_row + 16 * mt;
                const uint32_t ad = abuf + (uint32_t)r * 256
                                  + (((2 * s + a_hi) ^ (r & 7)) << 4);
                ldsm_x4(a[mt][0], a[mt][1], a[mt][2], a[mt][3], ad);
            }
            uint32_t b[8][2];
#pragma unroll
            for (int nt = 0; nt < 4; ++nt) {
                const int r = b_row + 16 * nt;
                const uint32_t bd = bbuf + (uint32_t)r * 256
                                  + (((2 * s + b_hi) ^ (r & 7)) << 4);
                ldsm_x4(b[2 * nt][0], b[2 * nt][1],
                        b[2 * nt + 1][0], b[2 * nt + 1][1], bd);
            }
#pragma unroll
            for (int mt = 0; mt < 2; ++mt)
#pragma unroll
                for (int n = 0; n < 8; ++n)
                    mma16816(acc[mt][n][0], acc[mt][n][1],
                             acc[mt][n][2], acc[mt][n][3],
                             a[mt][0], a[mt][1], a[mt][2], a[mt][3],
                             b[n][0], b[n][1]);
        }

        if (ch < NCHUNK - 1) {
            cp_wait0();
            __syncthreads();
        }
    }

    // ---- epilogue
#pragma unroll
    for (int mt = 0; mt < 2; ++mt) {
        const int row0 = rbase + m0 + mt * 16 + (lane >> 2);
#pragma unroll
        for (int n = 0; n < 8; ++n) {
            const int col = obase + n0 + n * 8 + 2 * (lane & 3);
            float2 v0; v0.x = acc[mt][n][0]; v0.y = acc[mt][n][1];
            float2 v1; v1.x = acc[mt][n][2]; v1.y = acc[mt][n][3];
            *reinterpret_cast<float2*>(out + (size_t)row0 * OUTFEAT + col) = v0;
            *reinterpret_cast<float2*>(out + (size_t)(row0 + 8) * OUTFEAT + col) = v1;
        }
    }
}

// ---------------------------------------------------------------- launch
extern "C" void kernel_launch(void* const* d_in, const int* in_sizes, int n_in,
                              void* d_out, int out_size)
{
    const float* input = (const float*)d_in[0];
    const int*   dims  = (const int*)  d_in[1];
    const float* thr   = (const float*)d_in[3];
    const float* lut   = (const float*)d_in[5];
    float*       out   = (float*)d_out;
    (void)in_sizes; (void)n_in; (void)out_size;

    cudaFuncSetAttribute(gemm_kernel,
                         cudaFuncAttributeMaxDynamicSharedMemorySize, SM_TOTAL);

    encode_kernel<<<NROWS, NCODE>>>(input, dims, thr);
    convert_kernel<<<(size_t)OUTFEAT * KGLOB / (256 * 8), 256>>>(lut);

    dim3 grid(OUTFEAT / 128, NROWS / 128);
    gemm_kernel<<<grid, 256, SM_TOTAL>>>(out);
}

// round 6
// speedup vs baseline: 1.5057x; 1.5057x over previous
#include <cuda_runtime.h>
#include <cuda_fp16.h>
#include <cstdint>

// Problem constants
#define NROWS   4096
#define INFEAT  4096
#define OUTFEAT 4096
#define NCODE   256
#define KLEAF   16
#define KGLOB   4096
// Aggregation tiling
#define TO      128
#define TN      128
#define CCH     8
#define NCHUNK  (NCODE / CCH)      // 32

// Static device scratch
__device__ __align__(16) unsigned char g_codes[NROWS * NCODE];          // 1 MB
__device__ __align__(16) __half        g_lutT[(size_t)KGLOB * OUTFEAT]; // 32 MB [k][o]

// ---------------------------------------------------------------------------
// Kernel 1: encode. One block per row, one thread per codebook.
// ---------------------------------------------------------------------------
__global__ void __launch_bounds__(NCODE) encode_kernel(
    const float* __restrict__ input,
    const int*   __restrict__ dims,
    const float* __restrict__ thr)
{
    const int n = blockIdx.x;
    const int c = threadIdx.x;
    const int4 d4 = *reinterpret_cast<const int4*>(dims + c * 4);
    const float* row = input + (size_t)n * INFEAT;
    const float x0 = __ldg(row + d4.x);
    const float x1 = __ldg(row + d4.y);
    const float x2 = __ldg(row + d4.z);
    const float x3 = __ldg(row + d4.w);
    const float* t = thr + c * 15;
    int i = 1;
    i = 2 * i + (x0 > __ldg(t + i - 1) ? 1 : 0);
    i = 2 * i + (x1 > __ldg(t + i - 1) ? 1 : 0);
    i = 2 * i + (x2 > __ldg(t + i - 1) ? 1 : 0);
    i = 2 * i + (x3 > __ldg(t + i - 1) ? 1 : 0);
    g_codes[n * NCODE + c] = (unsigned char)(i - 16);
}

// ---------------------------------------------------------------------------
// Kernel 1b: transpose + fp32->fp16 convert of lut: g_lutT[k][o] = half(lut[o][k])
// ---------------------------------------------------------------------------
__global__ void __launch_bounds__(256) transpose_kernel(
    const float* __restrict__ lut)
{
    __shared__ __half tile[64][66];

    const int k0 = blockIdx.x * 64;
    const int o0 = blockIdx.y * 64;
    const int tid = threadIdx.x;

#pragma unroll
    for (int j = 0; j < 16; ++j) {
        const int flat = j * 256 + tid;
        const int o = flat >> 6;
        const int k = flat & 63;
        tile[k][o] = __float2half(
            __ldg(lut + (size_t)(o0 + o) * KGLOB + k0 + k));
    }
    __syncthreads();
#pragma unroll
    for (int j = 0; j < 16; ++j) {
        const int flat = j * 256 + tid;
        const int k = flat >> 6;
        const int o = flat & 63;
        g_lutT[(size_t)(k0 + k) * OUTFEAT + o0 + o] = tile[k][o];
    }
}

// ---------------------------------------------------------------------------
// Kernel 2: LUT aggregation (fp16 SMEM gathers, half2 group-8 accumulation,
// fp32 fold per chunk).
// Block: 256 threads (8 warps). Tile: TO=128 outputs x TN=128 rows.
// SMEM: lut_s[idx][64] half2 (idx = cc*16 + code in [0,128)), row = 256 B.
// Lane owns outputs {2*lane, 2*lane+1, 64+2*lane, 64+2*lane+1}.
// ---------------------------------------------------------------------------
__global__ void __launch_bounds__(256, 2) agg_kernel(float* __restrict__ out)
{
    __shared__ __half2 lut_s[128 * 64];   // 32 KB

    const int o0   = blockIdx.x * TO;
    const int n0   = blockIdx.y * TN;
    const int tid  = threadIdx.x;
    const int warp = tid >> 5;
    const int lane = tid & 31;
    const int rowbase = n0 + warp * 16;

    // Byte base for gathers: this lane's half2 within an idx-row
    const char* lane_base = reinterpret_cast<const char*>(lut_s) + lane * 4;

    float acc[16][4];
#pragma unroll
    for (int t = 0; t < 16; ++t)
#pragma unroll
        for (int j = 0; j < 4; ++j) acc[t][j] = 0.0f;

    for (int ch = 0; ch < NCHUNK; ++ch) {
        const int c0 = ch * CCH;
        __syncthreads();   // previous chunk's readers done

        // Stage 128 idx-rows x 256 B (2048 uint4, 8 per thread), coalesced
#pragma unroll
        for (int i = 0; i < 8; ++i) {
            const int flat = i * 256 + tid;      // 0..2047
            const int idx  = flat >> 4;
            const int pos  = flat & 15;
            const uint4 v = *reinterpret_cast<const uint4*>(
                g_lutT + (size_t)(c0 * KLEAF + idx) * OUTFEAT + o0 + pos * 8);
            reinterpret_cast<uint4*>(lut_s)[flat] = v;
        }
        __syncthreads();

        // Gather-accumulate: fp16 pair sums across the 8 codebooks, then fold
#pragma unroll
        for (int t = 0; t < 16; ++t) {
            const int row = rowbase + t;
            const uint2 cw = *reinterpret_cast<const uint2*>(
                g_codes + (size_t)row * NCODE + c0);   // warp-uniform
            __half2 h01 = __float2half2_rn(0.0f);
            __half2 h23 = __float2half2_rn(0.0f);
#pragma unroll
            for (int cc = 0; cc < 8; ++cc) {
                const unsigned int w = (cc < 4) ? cw.x : cw.y;
                // PRMT: byte (cc&3) of w placed at result byte1 => code*256
                const unsigned int c256 =
                    __byte_perm(w, 0u, 0x4404u | (((unsigned)cc & 3u) << 4));
                const char* p = lane_base + cc * 4096 + c256;
                const __half2 v0 = *reinterpret_cast<const __half2*>(p);
                const __half2 v1 = *reinterpret_cast<const __half2*>(p + 128);
                h01 = __hadd2(h01, v0);
                h23 = __hadd2(h23, v1);
            }
            const float2 f0 = __half22float2(h01);
            const float2 f1 = __half22float2(h23);
            acc[t][0] += f0.x;
            acc[t][1] += f0.y;
            acc[t][2] += f1.x;
            acc[t][3] += f1.y;
        }
    }

    // Store: coalesced float2 writes
#pragma unroll
    for (int t = 0; t < 16; ++t) {
        float* orow = out + (size_t)(rowbase + t) * OUTFEAT + o0;
        float2 a; a.x = acc[t][0]; a.y = acc[t][1];
        float2 b; b.x = acc[t][2]; b.y = acc[t][3];
        *reinterpret_cast<float2*>(orow + 2 * lane)      = a;
        *reinterpret_cast<float2*>(orow + 64 + 2 * lane) = b;
    }
}

// ---------------------------------------------------------------------------
// Launch. Inputs: inputMatrix f32, dims i32, selection_matrix (unused),
// thresholds f32, tree_des_mat (unused), lut f32[4096][256][16].
// ---------------------------------------------------------------------------
extern "C" void kernel_launch(void* const* d_in, const int* in_sizes, int n_in,
                              void* d_out, int out_size)
{
    const float* input = (const float*)d_in[0];
    const int*   dims  = (const int*)  d_in[1];
    const float* thr   = (const float*)d_in[3];
    const float* lut   = (const float*)d_in[5];
    float*       out   = (float*)d_out;
    (void)in_sizes; (void)n_in; (void)out_size;

    encode_kernel<<<NROWS, NCODE>>>(input, dims, thr);

    dim3 tgrid(KGLOB / 64, OUTFEAT / 64);
    transpose_kernel<<<tgrid, 256>>>(lut);

    dim3 grid(OUTFEAT / TO, NROWS / TN);
    agg_kernel<<<grid, 256>>>(out);
}